// round 15
// baseline (speedup 1.0000x reference)
#include <cuda_runtime.h>
#include <cuda_fp16.h>
#include <cstdint>
#include <cstddef>

#define M_ROWS 32768
#define DIM    512
#define NCODES 4096

#define BM 128
#define BN 256
#define BK 32
#define NCH (DIM / BK)            // 16 chunks
#define NMT (M_ROWS / BM)         // 256
#define NNT2 (NCODES / BN)        // 16 n-tiles
#define TPB 256
#define THRESH 5e-3f

#define A_CHUNK 8192              // 128 rows x 32k fp16 swizzled image
#define B_CHUNK 16384             // 256 rows x 32k fp16 swizzled image
#define STAGE_BYTES (A_CHUNK + B_CHUNK)   // 24576
#define NSTAGE 4
#define SMEM_BYTES (1024 + NSTAGE * STAGE_BYTES)   // 99328

// ---------------- device scratch (allocation is forbidden) ----------------
__device__ __align__(128) unsigned char g_XA8[(size_t)NMT * NCH * A_CHUNK];  // 32MB
__device__ __align__(128) unsigned char g_WB8[(size_t)NNT2 * NCH * B_CHUNK]; // 4MB
__device__ __align__(128) float g_wnk[(size_t)NCODES * DIM];     // 8MB [n][k]
__device__ __align__(128) float g_whatT[DIM * NCODES];           // 8MB [k][n]
__device__ float  g_a[M_ROWS];
__device__ float  g_c[NCODES];
__device__ int    g_idx[M_ROWS];
__device__ float  g_bestv[M_ROWS];
__device__ unsigned long long g_cand1[(size_t)M_ROWS * NNT2];
__device__ float  g_cand2[(size_t)M_ROWS * NNT2];
__device__ unsigned long long g_key2[M_ROWS];
__device__ int    g_list[M_ROWS];
__device__ int    g_cnt;
__device__ double g_diff;

// ---------------- PTX helpers (base sm_90 features only, NO 'a') ----------
__device__ __forceinline__ uint32_t smem_u32(const void* p) {
    uint32_t a;
    asm("{ .reg .u64 t; cvta.to.shared.u64 t, %1; cvt.u32.u64 %0, t; }" : "=r"(a) : "l"(p));
    return a;
}
__device__ __forceinline__ void mbar_init(uint32_t m, uint32_t cnt) {
    asm volatile("mbarrier.init.shared.b64 [%0], %1;" :: "r"(m), "r"(cnt) : "memory");
}
__device__ __forceinline__ void mbar_expect_tx(uint32_t m, uint32_t bytes) {
    asm volatile("mbarrier.arrive.expect_tx.shared.b64 _, [%0], %1;" :: "r"(m), "r"(bytes) : "memory");
}
__device__ __forceinline__ void mbar_arrive(uint32_t m) {
    asm volatile("mbarrier.arrive.shared.b64 _, [%0];" :: "r"(m) : "memory");
}
__device__ __forceinline__ void mbar_wait(uint32_t m, uint32_t parity) {
    asm volatile(
        "{\n\t.reg .pred P;\n\t"
        "WL_%=:\n\t"
        "mbarrier.try_wait.parity.acquire.cta.shared::cta.b64 P, [%0], %1, 0x989680;\n\t"
        "@P bra WD_%=;\n\t"
        "bra WL_%=;\n\t"
        "WD_%=:\n\t}"
        :: "r"(m), "r"(parity) : "memory");
}
__device__ __forceinline__ void bulk_g2s(uint32_t dst, const void* src, uint32_t bytes, uint32_t mbar) {
    asm volatile(
        "cp.async.bulk.shared::cluster.global.mbarrier::complete_tx::bytes [%0], [%1], %2, [%3];"
        :: "r"(dst), "l"(src), "r"(bytes), "r"(mbar) : "memory");
}
__device__ __forceinline__ void fence_async_shared() {
    asm volatile("fence.proxy.async.shared::cta;" ::: "memory");
}
__device__ __forceinline__ void ldsm_x4(uint32_t* r, uint32_t addr) {
    asm volatile("ldmatrix.sync.aligned.m8n8.x4.shared.b16 {%0,%1,%2,%3}, [%4];"
                 : "=r"(r[0]), "=r"(r[1]), "=r"(r[2]), "=r"(r[3]) : "r"(addr));
}
__device__ __forceinline__ void mma16816(float* d, const uint32_t* a, const uint32_t* b) {
    asm volatile(
        "mma.sync.aligned.m16n8k16.row.col.f32.f16.f16.f32 "
        "{%0,%1,%2,%3}, {%4,%5,%6,%7}, {%8,%9}, {%0,%1,%2,%3};"
        : "+f"(d[0]), "+f"(d[1]), "+f"(d[2]), "+f"(d[3])
        : "r"(a[0]), "r"(a[1]), "r"(a[2]), "r"(a[3]), "r"(b[0]), "r"(b[1]));
}
__device__ __forceinline__ uint32_t sw_off(int row, int g) {
    return (uint32_t)row * 64u + (uint32_t)((g ^ ((row >> 1) & 3)) << 4);
}
__device__ __forceinline__ uint2 pack4h(const float* v) {
    unsigned short h[4];
#pragma unroll
    for (int i = 0; i < 4; i++) h[i] = __half_as_ushort(__float2half_rn(v[i]));
    uint2 q;
    q.x = (uint32_t)h[0] | ((uint32_t)h[1] << 16);
    q.y = (uint32_t)h[2] | ((uint32_t)h[3] << 16);
    return q;
}
// A image: 128-row tiles, 8KB per (tile,kc)
__device__ __forceinline__ size_t img_off_a(int tile, int row, int k) {
    const int kc = k >> 5, kq = k & 31;
    return ((size_t)(tile * NCH + kc) * A_CHUNK) + sw_off(row, kq >> 3) + (kq & 7) * 2;
}
// B image: 256-row tiles, 16KB per (tile,kc)
__device__ __forceinline__ size_t img_off_b(int tile, int row, int k) {
    const int kc = k >> 5, kq = k & 31;
    return ((size_t)(tile * NCH + kc) * B_CHUNK) + sw_off(row, kq >> 3) + (kq & 7) * 2;
}

// =====================================================================
// Launch 1 — xprep: fused plane writer + bit-exact a[m] (unchanged math).
// =====================================================================
__global__ void __launch_bounds__(256) xprep_kernel(const float* __restrict__ x) {
    __shared__ float xs[32 * 513];
    const int t = threadIdx.x;
    const int m0 = blockIdx.x * 32;

    for (int i = t; i < 32 * 128; i += 256) {
        const int row = i >> 7, c4 = i & 127;
        float4 v = reinterpret_cast<const float4*>(x + (size_t)(m0 + row) * DIM)[c4];
        float* d = xs + row * 513 + c4 * 4;
        d[0] = v.x; d[1] = v.y; d[2] = v.z; d[3] = v.w;
    }
    __syncthreads();

    for (int i = t; i < 32 * 128; i += 256) {
        const int row = i >> 7, c4 = i & 127;
        const int m = m0 + row;
        const float* s = xs + row * 513 + c4 * 4;
        float vv[4] = {s[0], s[1], s[2], s[3]};
        *reinterpret_cast<uint2*>(g_XA8 + img_off_a(m >> 7, m & 127, 4 * c4)) = pack4h(vv);
    }

    if (t < 128) {
        const int m = t >> 2, p = t & 3;
        const float* xr = xs + m * 513 + p * 128;
        double s0 = 0.0, s1 = 0.0;
#pragma unroll 8
        for (int k = 0; k < 128; k += 2) {
            float u0 = xr[k];
            float u1 = xr[k + 1];
            s0 += (double)u0 * u0;
            s1 += (double)u1 * u1;
        }
        const double part = s0 + s1;
        const double p1 = __shfl_down_sync(0xffffffff, part, 1);
        const double p2 = __shfl_down_sync(0xffffffff, part, 2);
        const double p3 = __shfl_down_sync(0xffffffff, part, 3);
        if (p == 0)
            g_a[m0 + m] = (float)(((part + p1) + p2) + p3);
    }
    if (blockIdx.x == 0 && t == 0) { g_cnt = 0; g_diff = 0.0; }
}

// =====================================================================
// Launch 2 — prepw: bit-exact R2 math; 256-row B images.
// =====================================================================
__global__ void prepw_kernel(const float* __restrict__ ew) {
    __shared__ double sred[128];
    const int n = blockIdx.x, t = threadIdx.x;

    float4 v = reinterpret_cast<const float4*>(ew + (size_t)n * DIM)[t];
    double s = (double)v.x * v.x + (double)v.y * v.y +
               (double)v.z * v.z + (double)v.w * v.w;
    sred[t] = s;
    __syncthreads();
    for (int o = 64; o; o >>= 1) { if (t < o) sred[t] += sred[t + o]; __syncthreads(); }
    const float norm = sqrtf((float)sred[0]);
    __syncthreads();

    const float w0 = __fdiv_rn(v.x, norm);
    const float w1 = __fdiv_rn(v.y, norm);
    const float w2 = __fdiv_rn(v.z, norm);
    const float w3 = __fdiv_rn(v.w, norm);

    reinterpret_cast<float4*>(g_wnk + (size_t)n * DIM)[t] = make_float4(w0, w1, w2, w3);

    double c = (double)w0 * w0 + (double)w1 * w1 +
               (double)w2 * w2 + (double)w3 * w3;
    sred[t] = c;
    __syncthreads();
    for (int o = 64; o; o >>= 1) { if (t < o) sred[t] += sred[t + o]; __syncthreads(); }
    if (t == 0) g_c[n] = (float)sred[0];

    float wv[4] = {w0, w1, w2, w3};
    const int ntile = n >> 8, row = n & 255;
    *reinterpret_cast<uint2*>(g_WB8 + img_off_b(ntile, row, 4 * t)) = pack4h(wv);
}

// =====================================================================
// Launch 3 — transpose g_wnk[n][k] -> g_whatT[k][n].
// =====================================================================
__global__ void transpose_kernel() {
    __shared__ float ts[32][33];
    const int bn = blockIdx.x >> 4, bk = blockIdx.x & 15;
    const int n0 = bn * 32, k0 = bk * 32;
    const int r = threadIdx.x >> 3;
    const int c = (threadIdx.x & 7) * 4;

    float4 v = *reinterpret_cast<const float4*>(g_wnk + (size_t)(n0 + r) * DIM + k0 + c);
    ts[r][c + 0] = v.x;
    ts[r][c + 1] = v.y;
    ts[r][c + 2] = v.z;
    ts[r][c + 3] = v.w;
    __syncthreads();

    const int kk = threadIdx.x >> 3;
    const int nn = (threadIdx.x & 7) * 4;
    float4 o = make_float4(ts[nn + 0][kk], ts[nn + 1][kk],
                           ts[nn + 2][kk], ts[nn + 3][kk]);
    *reinterpret_cast<float4*>(g_whatT + (size_t)(k0 + kk) * NCODES + n0 + nn) = o;
}

// =====================================================================
// Launch 4 (PROFILED SLOT) — HMMA GEMM 128x256x(512), warp tile 64x64.
// Warp grid 2m x 4n (R8-verified layout); bulk-DMA feed; per-CTA top-2.
// =====================================================================
__global__ void __launch_bounds__(TPB, 1) mma_topcand_kernel() {
    extern __shared__ unsigned char smraw[];
    const uint32_t sbase = smem_u32(smraw);
    const uint32_t stg = sbase + 1024;

    const int tid = threadIdx.x;
    const int wid = tid >> 5, lid = tid & 31;
    const int wm = wid & 1, wn = wid >> 1;          // warp tile 64m x 64n
    const int g = lid >> 2, tq = lid & 3;
    const int ntile = blockIdx.x & (NNT2 - 1);
    const int mtile = blockIdx.x >> 4;

    const unsigned char* Asrc = g_XA8 + (size_t)mtile * NCH * A_CHUNK;
    const unsigned char* Bsrc = g_WB8 + (size_t)ntile * NCH * B_CHUNK;

    if (tid == 0) {
#pragma unroll
        for (int s = 0; s < NSTAGE; s++) {
            mbar_init(sbase + s * 8, 1);
            mbar_init(sbase + 64 + s * 8, 8);
        }
    }
    __syncthreads();
    fence_async_shared();

    if (tid == 0) {
#pragma unroll
        for (int kc = 0; kc < NSTAGE; kc++) {
            mbar_expect_tx(sbase + kc * 8, STAGE_BYTES);
            bulk_g2s(stg + kc * STAGE_BYTES,           Asrc + (size_t)kc * A_CHUNK,
                     A_CHUNK, sbase + kc * 8);
            bulk_g2s(stg + kc * STAGE_BYTES + A_CHUNK, Bsrc + (size_t)kc * B_CHUNK,
                     B_CHUNK, sbase + kc * 8);
        }
    }

    float acc[4][8][4];
#pragma unroll
    for (int i = 0; i < 4; i++)
#pragma unroll
        for (int j = 0; j < 8; j++)
#pragma unroll
            for (int k = 0; k < 4; k++) acc[i][j][k] = 0.0f;

    for (int kc = 0; kc < NCH; kc++) {
        const int s = kc % NSTAGE;
        const uint32_t ph = (uint32_t)(kc / NSTAGE) & 1u;
        mbar_wait(sbase + s * 8, ph);
        const uint32_t sa = stg + s * STAGE_BYTES;
        const uint32_t sb = sa + A_CHUNK;

#pragma unroll
        for (int ks = 0; ks < 2; ks++) {
            uint32_t af[4][4];
#pragma unroll
            for (int mt = 0; mt < 4; mt++) {
                const int row = wm * 64 + mt * 16 + (lid & 15);
                const int gg = ks * 2 + (lid >> 4);
                ldsm_x4(af[mt], sa + sw_off(row, gg));
            }
            uint32_t bf[4][4];
#pragma unroll
            for (int h = 0; h < 4; h++) {       // covers 8 n-subtiles (64 cols)
                const int nsub = (lid >> 4) + h * 2;
                const int row = wn * 64 + nsub * 8 + (lid & 7);
                const int gg = ks * 2 + ((lid >> 3) & 1);
                ldsm_x4(bf[h], sb + sw_off(row, gg));
            }
#pragma unroll
            for (int mt = 0; mt < 4; mt++)
#pragma unroll
                for (int nt = 0; nt < 8; nt++)
                    mma16816(acc[mt][nt], af[mt], &bf[nt >> 1][(nt & 1) * 2]);
        }

        if (lid == 0) mbar_arrive(sbase + 64 + s * 8);
        if (tid == 0 && kc + NSTAGE < NCH) {
            mbar_wait(sbase + 64 + s * 8, ph);
            const int nk = kc + NSTAGE;
            mbar_expect_tx(sbase + s * 8, STAGE_BYTES);
            bulk_g2s(stg + s * STAGE_BYTES,           Asrc + (size_t)nk * A_CHUNK,
                     A_CHUNK, sbase + s * 8);
            bulk_g2s(stg + s * STAGE_BYTES + A_CHUNK, Bsrc + (size_t)nk * B_CHUNK,
                     B_CHUNK, sbase + s * 8);
        }
    }

    // ---------------- epilogue: dist + top-2 (R8-verified n mapping) ----
    const float* ga = g_a + mtile * BM;
    float v1[8], v2[8];
    int i1[8];
#pragma unroll
    for (int i = 0; i < 8; i++) {
        v1[i] = __int_as_float(0x7f800000);
        v2[i] = __int_as_float(0x7f800000);
        i1[i] = 0;
    }

#pragma unroll
    for (int mt = 0; mt < 4; mt++)
#pragma unroll
        for (int rh = 0; rh < 2; rh++) {
            const int r = mt * 2 + rh;
            const float a = ga[wm * 64 + mt * 16 + g + rh * 8];
#pragma unroll
            for (int nt = 0; nt < 8; nt++)
#pragma unroll
                for (int cc = 0; cc < 2; cc++) {
                    const float b = acc[mt][nt][rh * 2 + cc];
                    const int n = ntile * BN + wn * 64 + nt * 8 + 2 * tq + cc;
                    const float d = __fadd_rn(__fadd_rn(a, -__fmul_rn(2.0f, b)), g_c[n]);
                    if (d < v1[r]) { v2[r] = v1[r]; v1[r] = d; i1[r] = n; }
                    else if (d < v2[r]) { v2[r] = d; }
                }
        }

#pragma unroll
    for (int i = 0; i < 8; i++) {
#pragma unroll
        for (int ofs = 1; ofs <= 2; ofs <<= 1) {
            const float ov1 = __shfl_xor_sync(0xffffffff, v1[i], ofs);
            const int   oi1 = __shfl_xor_sync(0xffffffff, i1[i], ofs);
            const float ov2 = __shfl_xor_sync(0xffffffff, v2[i], ofs);
            float loser;
            if (ov1 < v1[i] || (ov1 == v1[i] && oi1 < i1[i])) {
                loser = v1[i]; v1[i] = ov1; i1[i] = oi1;
            } else {
                loser = ov1;
            }
            v2[i] = fminf(fminf(v2[i], ov2), loser);
        }
    }

    __syncthreads();
    float* cv1 = reinterpret_cast<float*>(smraw + 1024);
    int*   ci1 = reinterpret_cast<int*>(smraw + 1024 + 2048);
    float* cv2 = reinterpret_cast<float*>(smraw + 1024 + 4096);
    if (tq == 0) {
#pragma unroll
        for (int mt = 0; mt < 4; mt++)
#pragma unroll
            for (int rh = 0; rh < 2; rh++) {
                const int ml = wm * 64 + mt * 16 + g + rh * 8;
                const int r = mt * 2 + rh;
                cv1[ml * 4 + wn] = v1[r];
                ci1[ml * 4 + wn] = i1[r];
                cv2[ml * 4 + wn] = v2[r];
            }
    }
    __syncthreads();
    if (tid < BM) {
        float bv1 = cv1[tid * 4], bv2 = cv2[tid * 4];
        int bi = ci1[tid * 4];
#pragma unroll
        for (int w = 1; w < 4; w++) {
            const float ov1 = cv1[tid * 4 + w], ov2 = cv2[tid * 4 + w];
            const int oi = ci1[tid * 4 + w];
            float loser;
            if (ov1 < bv1 || (ov1 == bv1 && oi < bi)) { loser = bv1; bv1 = ov1; bi = oi; }
            else loser = ov1;
            bv2 = fminf(fminf(bv2, ov2), loser);
        }
        const size_t slot = (size_t)(mtile * BM + tid) * NNT2 + ntile;
        g_cand1[slot] = ((unsigned long long)__float_as_uint(bv1) << 32) | (unsigned)bi;
        g_cand2[slot] = bv2;
    }
}

// =====================================================================
// Launch 5 — flag: 16 tile candidates; near-ties -> refine list.
// =====================================================================
__global__ void flag_kernel() {
    const int tid = threadIdx.x, lane = tid & 31;
    const int m = blockIdx.x * 8 + (tid >> 5);

    unsigned long long key = ~0ull;
    float mv2 = __int_as_float(0x7f800000);
    if (lane < NNT2) {
        key = g_cand1[(size_t)m * NNT2 + lane];
        mv2 = g_cand2[(size_t)m * NNT2 + lane];
    }

    unsigned long long bkey = key;
#pragma unroll
    for (int o = 16; o; o >>= 1) {
        unsigned long long ok = __shfl_xor_sync(0xffffffff, bkey, o);
        if (ok < bkey) bkey = ok;
    }
    const float bv = __uint_as_float((unsigned)(bkey >> 32));
    float cand2 = (key == bkey) ? mv2 : fminf(__uint_as_float((unsigned)(key >> 32)), mv2);
#pragma unroll
    for (int o = 16; o; o >>= 1)
        cand2 = fminf(cand2, __shfl_xor_sync(0xffffffff, cand2, o));

    if (lane == 0) {
        g_idx[m] = (int)(bkey & 0xffffffffu);
        if (__fadd_rn(cand2, -bv) < THRESH) {
            g_key2[m] = ~0ull;
            g_bestv[m] = bv;
            const int pos = atomicAdd(&g_cnt, 1);
            g_list[pos] = m;
        }
    }
}

// =====================================================================
// Launch 6 — refine: tile-restricted exact refine, 256-code tiles.
// Thread t covers codes nt*256+t and nt*256+128+t (independent exact
// k-ascending fp32 FMA chains; lower index wins ties).
// =====================================================================
__global__ void __launch_bounds__(128) refine_kernel(const float* __restrict__ x) {
    __shared__ float xs[DIM];
    __shared__ float wv[4];
    __shared__ int   wi[4];
    const int nt = blockIdx.x & (NNT2 - 1);
    const int slot = blockIdx.x >> 4;     // 0..1023
    const int t = threadIdx.x;
    const int cnt = g_cnt;

    for (int ri = slot; ri < cnt; ri += 1024) {
        const int m = g_list[ri];
        const float c1v =
            __uint_as_float((unsigned)(g_cand1[(size_t)m * NNT2 + nt] >> 32));
        if (c1v > __fadd_rn(g_bestv[m], THRESH)) continue;

        __syncthreads();
        {
            float4 v = reinterpret_cast<const float4*>(x + (size_t)m * DIM)[t];
            xs[4 * t + 0] = v.x;
            xs[4 * t + 1] = v.y;
            xs[4 * t + 2] = v.z;
            xs[4 * t + 3] = v.w;
        }
        __syncthreads();

        const int n1 = nt * BN + t;
        const int n2 = n1 + 128;
        float b1 = 0.0f, b2 = 0.0f;
#pragma unroll 8
        for (int k = 0; k < DIM; k++) {
            const float xv = xs[k];
            b1 = __fmaf_rn(xv, g_whatT[(size_t)k * NCODES + n1], b1);
            b2 = __fmaf_rn(xv, g_whatT[(size_t)k * NCODES + n2], b2);
        }
        const float a = g_a[m];
        const float d1 = __fadd_rn(__fadd_rn(a, -__fmul_rn(2.0f, b1)), g_c[n1]);
        const float d2 = __fadd_rn(__fadd_rn(a, -__fmul_rn(2.0f, b2)), g_c[n2]);
        float v = d1;
        int ix = n1;
        if (d2 < v) { v = d2; ix = n2; }   // tie keeps n1 (lower index)

#pragma unroll
        for (int o = 16; o; o >>= 1) {
            const float ov = __shfl_xor_sync(0xffffffff, v, o);
            const int oi = __shfl_xor_sync(0xffffffff, ix, o);
            if (ov < v || (ov == v && oi < ix)) { v = ov; ix = oi; }
        }
        if ((t & 31) == 0) { wv[t >> 5] = v; wi[t >> 5] = ix; }
        __syncthreads();
        if (t == 0) {
#pragma unroll
            for (int w2 = 1; w2 < 4; w2++) {
                if (wv[w2] < v || (wv[w2] == v && wi[w2] < ix)) { v = wv[w2]; ix = wi[w2]; }
            }
            atomicMin(&g_key2[m],
                      ((unsigned long long)__float_as_uint(v) << 32) | (unsigned)ix);
        }
    }
}

// launch 7
__global__ void apply_kernel() {
    const int cnt = g_cnt;
    for (int i = blockIdx.x * 256 + threadIdx.x; i < cnt; i += gridDim.x * 256) {
        const int m = g_list[i];
        g_idx[m] = (int)(g_key2[m] & 0xffffffffu);
    }
}

// =====================================================================
// Launch 8 — gather: fp32 per-thread diff partials.
// =====================================================================
__global__ void gather_kernel(const float* __restrict__ x,
                              const float* __restrict__ ew,
                              float* __restrict__ out) {
    __shared__ double ss[8];
    const int w = threadIdx.x >> 5, l = threadIdx.x & 31;
    const int m = blockIdx.x * 8 + w;
    const int idx = g_idx[m];

    const float4* qr = reinterpret_cast<const float4*>(ew + (size_t)idx * DIM);
    const float4* xr = reinterpret_cast<const float4*>(x + (size_t)m * DIM);
    float4* orow = reinterpret_cast<float4*>(out) + (size_t)m * (DIM / 4);

    float sf = 0.0f;
#pragma unroll
    for (int p = 0; p < 4; p++) {
        const int c = l + p * 32;
        float4 q = qr[c];
        float4 xv = xr[c];
        float4 o;
        float e, q1;
        e = __fadd_rn(q.x, -xv.x); q1 = __fadd_rn(xv.x, e);
        o.x = __fmul_rn(__fadd_rn(q.x, q1), 0.5f); sf = __fmaf_rn(e, e, sf);
        e = __fadd_rn(q.y, -xv.y); q1 = __fadd_rn(xv.y, e);
        o.y = __fmul_rn(__fadd_rn(q.y, q1), 0.5f); sf = __fmaf_rn(e, e, sf);
        e = __fadd_rn(q.z, -xv.z); q1 = __fadd_rn(xv.z, e);
        o.z = __fmul_rn(__fadd_rn(q.z, q1), 0.5f); sf = __fmaf_rn(e, e, sf);
        e = __fadd_rn(q.w, -xv.w); q1 = __fadd_rn(xv.w, e);
        o.w = __fmul_rn(__fadd_rn(q.w, q1), 0.5f); sf = __fmaf_rn(e, e, sf);
        orow[c] = o;
    }
    double s = (double)sf;
#pragma unroll
    for (int o = 16; o; o >>= 1)
        s += __shfl_xor_sync(0xffffffff, s, o);
    if (l == 0) ss[w] = s;
    __syncthreads();
    if (threadIdx.x == 0) {
        double t = 0.0;
#pragma unroll
        for (int i = 0; i < 8; i++) t += ss[i];
        atomicAdd(&g_diff, t);
    }
}

// launch 9
__global__ void final_kernel(float* __restrict__ out, int write_scalar) {
    if (write_scalar)
        out[(size_t)M_ROWS * DIM] = (float)(g_diff / (double)((size_t)M_ROWS * DIM));
}

// =====================================================================
extern "C" void kernel_launch(void* const* d_in, const int* in_sizes, int n_in,
                              void* d_out, int out_size) {
    const float* x  = (const float*)d_in[0];
    const float* ew = (const float*)d_in[1];
    if (n_in >= 2 && in_sizes[0] == NCODES * DIM && in_sizes[1] == M_ROWS * DIM) {
        ew = (const float*)d_in[0];
        x  = (const float*)d_in[1];
    }
    float* out = (float*)d_out;

    cudaFuncSetAttribute(mma_topcand_kernel,
                         cudaFuncAttributeMaxDynamicSharedMemorySize, SMEM_BYTES);

    xprep_kernel<<<M_ROWS / 32, 256>>>(x);                    // 1
    prepw_kernel<<<NCODES, 128>>>(ew);                        // 2
    transpose_kernel<<<2048, 256>>>();                        // 3
    mma_topcand_kernel<<<NMT * NNT2, TPB, SMEM_BYTES>>>();    // 4 <- profiled
    flag_kernel<<<M_ROWS / 8, 256>>>();                       // 5
    refine_kernel<<<NNT2 * 1024, 128>>>(x);                   // 6
    apply_kernel<<<32, 256>>>();                              // 7
    gather_kernel<<<M_ROWS / 8, 256>>>(x, ew, out);           // 8
    const int write_scalar = (out_size > M_ROWS * DIM) ? 1 : 0;
    final_kernel<<<1, 1>>>(out, write_scalar);                // 9
}

// round 16
// speedup vs baseline: 1.2345x; 1.2345x over previous
#include <cuda_runtime.h>
#include <cuda_fp16.h>
#include <cstdint>
#include <cstddef>

#define M_ROWS 32768
#define DIM    512
#define NCODES 4096

#define BM 128
#define BN 128
#define BK 32
#define NCH (DIM / BK)            // 16 chunks
#define NMT (M_ROWS / BM)         // 256
#define NNT (NCODES / BN)         // 32
#define TPB 256
#define THRESH 5e-3f

#define CHUNK_BYTES 8192
#define STAGE_BYTES (2 * CHUNK_BYTES)
#define NSTAGE 4
#define SMEM_BYTES (1024 + NSTAGE * STAGE_BYTES)   // 66560

// ---------------- device scratch (allocation is forbidden) ----------------
__device__ __align__(128) unsigned char g_XA8[(size_t)NMT * NCH * CHUNK_BYTES]; // 32MB
__device__ __align__(128) unsigned char g_WB8[(size_t)NNT * NCH * CHUNK_BYTES]; // 4MB
__device__ __align__(128) float g_wnk[(size_t)NCODES * DIM];     // 8MB [n][k]
__device__ __align__(128) float g_whatT[DIM * NCODES];           // 8MB [k][n]
__device__ float  g_a[M_ROWS];
__device__ float  g_c[NCODES];
__device__ int    g_idx[M_ROWS];
__device__ float  g_bestv[M_ROWS];
__device__ unsigned long long g_cand1[(size_t)M_ROWS * NNT];
__device__ float  g_cand2[(size_t)M_ROWS * NNT];
__device__ unsigned long long g_key2[M_ROWS];
__device__ int    g_list[M_ROWS];
__device__ int    g_cnt;
__device__ double g_diff;

// ---------------- PTX helpers (base sm_90 features only, NO 'a') ----------
__device__ __forceinline__ uint32_t smem_u32(const void* p) {
    uint32_t a;
    asm("{ .reg .u64 t; cvta.to.shared.u64 t, %1; cvt.u32.u64 %0, t; }" : "=r"(a) : "l"(p));
    return a;
}
__device__ __forceinline__ void mbar_init(uint32_t m, uint32_t cnt) {
    asm volatile("mbarrier.init.shared.b64 [%0], %1;" :: "r"(m), "r"(cnt) : "memory");
}
__device__ __forceinline__ void mbar_expect_tx(uint32_t m, uint32_t bytes) {
    asm volatile("mbarrier.arrive.expect_tx.shared.b64 _, [%0], %1;" :: "r"(m), "r"(bytes) : "memory");
}
__device__ __forceinline__ void mbar_arrive(uint32_t m) {
    asm volatile("mbarrier.arrive.shared.b64 _, [%0];" :: "r"(m) : "memory");
}
__device__ __forceinline__ void mbar_wait(uint32_t m, uint32_t parity) {
    asm volatile(
        "{\n\t.reg .pred P;\n\t"
        "WL_%=:\n\t"
        "mbarrier.try_wait.parity.acquire.cta.shared::cta.b64 P, [%0], %1, 0x989680;\n\t"
        "@P bra WD_%=;\n\t"
        "bra WL_%=;\n\t"
        "WD_%=:\n\t}"
        :: "r"(m), "r"(parity) : "memory");
}
__device__ __forceinline__ void bulk_g2s(uint32_t dst, const void* src, uint32_t bytes, uint32_t mbar) {
    asm volatile(
        "cp.async.bulk.shared::cluster.global.mbarrier::complete_tx::bytes [%0], [%1], %2, [%3];"
        :: "r"(dst), "l"(src), "r"(bytes), "r"(mbar) : "memory");
}
__device__ __forceinline__ void fence_async_shared() {
    asm volatile("fence.proxy.async.shared::cta;" ::: "memory");
}
__device__ __forceinline__ void ldsm_x4(uint32_t* r, uint32_t addr) {
    asm volatile("ldmatrix.sync.aligned.m8n8.x4.shared.b16 {%0,%1,%2,%3}, [%4];"
                 : "=r"(r[0]), "=r"(r[1]), "=r"(r[2]), "=r"(r[3]) : "r"(addr));
}
__device__ __forceinline__ void mma16816(float* d, const uint32_t* a, const uint32_t* b) {
    asm volatile(
        "mma.sync.aligned.m16n8k16.row.col.f32.f16.f16.f32 "
        "{%0,%1,%2,%3}, {%4,%5,%6,%7}, {%8,%9}, {%0,%1,%2,%3};"
        : "+f"(d[0]), "+f"(d[1]), "+f"(d[2]), "+f"(d[3])
        : "r"(a[0]), "r"(a[1]), "r"(a[2]), "r"(a[3]), "r"(b[0]), "r"(b[1]));
}
__device__ __forceinline__ uint32_t sw_off(int row, int g) {
    return (uint32_t)row * 64u + (uint32_t)((g ^ ((row >> 1) & 3)) << 4);
}
__device__ __forceinline__ uint2 pack4h(const float* v) {
    unsigned short h[4];
#pragma unroll
    for (int i = 0; i < 4; i++) h[i] = __half_as_ushort(__float2half_rn(v[i]));
    uint2 q;
    q.x = (uint32_t)h[0] | ((uint32_t)h[1] << 16);
    q.y = (uint32_t)h[2] | ((uint32_t)h[3] << 16);
    return q;
}
__device__ __forceinline__ size_t img_off(int tile, int row, int k) {
    const int kc = k >> 5;
    const int kq = k & 31;
    return ((size_t)(tile * NCH + kc) << 13) + sw_off(row, kq >> 3) + (kq & 7) * 2;
}

// =====================================================================
// Launch 1 — xprep: fused plane writer + bit-exact a[m].
// =====================================================================
__global__ void __launch_bounds__(256) xprep_kernel(const float* __restrict__ x) {
    __shared__ float xs[32 * 513];
    const int t = threadIdx.x;
    const int m0 = blockIdx.x * 32;

    for (int i = t; i < 32 * 128; i += 256) {
        const int row = i >> 7, c4 = i & 127;
        float4 v = reinterpret_cast<const float4*>(x + (size_t)(m0 + row) * DIM)[c4];
        float* d = xs + row * 513 + c4 * 4;
        d[0] = v.x; d[1] = v.y; d[2] = v.z; d[3] = v.w;
    }
    __syncthreads();

    for (int i = t; i < 32 * 128; i += 256) {
        const int row = i >> 7, c4 = i & 127;
        const int m = m0 + row;
        const float* s = xs + row * 513 + c4 * 4;
        float vv[4] = {s[0], s[1], s[2], s[3]};
        *reinterpret_cast<uint2*>(g_XA8 + img_off(m >> 7, m & 127, 4 * c4)) = pack4h(vv);
    }

    if (t < 128) {
        const int m = t >> 2, p = t & 3;
        const float* xr = xs + m * 513 + p * 128;
        double s0 = 0.0, s1 = 0.0;
#pragma unroll 8
        for (int k = 0; k < 128; k += 2) {
            float u0 = xr[k];
            float u1 = xr[k + 1];
            s0 += (double)u0 * u0;
            s1 += (double)u1 * u1;
        }
        const double part = s0 + s1;
        const double p1 = __shfl_down_sync(0xffffffff, part, 1);
        const double p2 = __shfl_down_sync(0xffffffff, part, 2);
        const double p3 = __shfl_down_sync(0xffffffff, part, 3);
        if (p == 0)
            g_a[m0 + m] = (float)(((part + p1) + p2) + p3);
    }
    if (blockIdx.x == 0 && t == 0) { g_cnt = 0; g_diff = 0.0; }
}

// =====================================================================
// Launch 2 — prepw: bit-exact R2 math; coalesced g_wnk write.
// =====================================================================
__global__ void prepw_kernel(const float* __restrict__ ew) {
    __shared__ double sred[128];
    const int n = blockIdx.x, t = threadIdx.x;

    float4 v = reinterpret_cast<const float4*>(ew + (size_t)n * DIM)[t];
    double s = (double)v.x * v.x + (double)v.y * v.y +
               (double)v.z * v.z + (double)v.w * v.w;
    sred[t] = s;
    __syncthreads();
    for (int o = 64; o; o >>= 1) { if (t < o) sred[t] += sred[t + o]; __syncthreads(); }
    const float norm = sqrtf((float)sred[0]);
    __syncthreads();

    const float w0 = __fdiv_rn(v.x, norm);
    const float w1 = __fdiv_rn(v.y, norm);
    const float w2 = __fdiv_rn(v.z, norm);
    const float w3 = __fdiv_rn(v.w, norm);

    reinterpret_cast<float4*>(g_wnk + (size_t)n * DIM)[t] = make_float4(w0, w1, w2, w3);

    double c = (double)w0 * w0 + (double)w1 * w1 +
               (double)w2 * w2 + (double)w3 * w3;
    sred[t] = c;
    __syncthreads();
    for (int o = 64; o; o >>= 1) { if (t < o) sred[t] += sred[t + o]; __syncthreads(); }
    if (t == 0) g_c[n] = (float)sred[0];

    float wv[4] = {w0, w1, w2, w3};
    const int ntile = n >> 7, row = n & 127;
    *reinterpret_cast<uint2*>(g_WB8 + img_off(ntile, row, 4 * t)) = pack4h(wv);
}

// =====================================================================
// Launch 3 — transpose g_wnk[n][k] -> g_whatT[k][n].
// =====================================================================
__global__ void transpose_kernel() {
    __shared__ float ts[32][33];
    const int bn = blockIdx.x >> 4, bk = blockIdx.x & 15;
    const int n0 = bn * 32, k0 = bk * 32;
    const int r = threadIdx.x >> 3;
    const int c = (threadIdx.x & 7) * 4;

    float4 v = *reinterpret_cast<const float4*>(g_wnk + (size_t)(n0 + r) * DIM + k0 + c);
    ts[r][c + 0] = v.x;
    ts[r][c + 1] = v.y;
    ts[r][c + 2] = v.z;
    ts[r][c + 3] = v.w;
    __syncthreads();

    const int kk = threadIdx.x >> 3;
    const int nn = (threadIdx.x & 7) * 4;
    float4 o = make_float4(ts[nn + 0][kk], ts[nn + 1][kk],
                           ts[nn + 2][kk], ts[nn + 3][kk]);
    *reinterpret_cast<float4*>(g_whatT + (size_t)(k0 + kk) * NCODES + n0 + nn) = o;
}

// =====================================================================
// Launch 4 (PROFILED SLOT) — HMMA GEMM 128x128, occ 2, unrolled stages.
// Chunk loop: outer kb += NSTAGE, inner s fully unrolled -> all SMEM
// addresses & barrier offsets are compile-time constants.
// =====================================================================
__global__ void __launch_bounds__(TPB, 2) mma_topcand_kernel() {
    extern __shared__ unsigned char smraw[];
    const uint32_t sbase = smem_u32(smraw);
    const uint32_t stg = sbase + 1024;

    const int tid = threadIdx.x;
    const int wid = tid >> 5, lid = tid & 31;
    const int wm = wid & 1, wn = wid >> 1;
    const int g = lid >> 2, tq = lid & 3;
    const int ntile = blockIdx.x & (NNT - 1);
    const int mtile = blockIdx.x >> 5;

    const unsigned char* Asrc = g_XA8 + ((size_t)mtile * NCH << 13);
    const unsigned char* Bsrc = g_WB8 + ((size_t)ntile * NCH << 13);

    if (tid == 0) {
#pragma unroll
        for (int s = 0; s < NSTAGE; s++) {
            mbar_init(sbase + s * 8, 1);
            mbar_init(sbase + 64 + s * 8, 8);
        }
    }
    __syncthreads();
    fence_async_shared();

    if (tid == 0) {
#pragma unroll
        for (int kc = 0; kc < NSTAGE; kc++) {
            mbar_expect_tx(sbase + kc * 8, STAGE_BYTES);
            bulk_g2s(stg + kc * STAGE_BYTES,               Asrc + ((size_t)kc << 13),
                     CHUNK_BYTES, sbase + kc * 8);
            bulk_g2s(stg + kc * STAGE_BYTES + CHUNK_BYTES, Bsrc + ((size_t)kc << 13),
                     CHUNK_BYTES, sbase + kc * 8);
        }
    }

    // per-thread ldsm lane geometry (loop-invariant)
    const int a_row = wm * 64 + (lid & 15);       // + mt*16
    const int a_gsel = lid >> 4;                  // + ks*2
    const int b_row = wn * 32 + ((lid >> 4) * 8) + (lid & 7);  // + h*16
    const int b_gsel = (lid >> 3) & 1;            // + ks*2

    float acc[4][4][4];
#pragma unroll
    for (int i = 0; i < 4; i++)
#pragma unroll
        for (int j = 0; j < 4; j++)
#pragma unroll
            for (int k = 0; k < 4; k++) acc[i][j][k] = 0.0f;

    for (int kb = 0; kb < NCH; kb += NSTAGE) {
        const uint32_t ph = ((uint32_t)kb / NSTAGE) & 1u;
#pragma unroll
        for (int s = 0; s < NSTAGE; s++) {
            mbar_wait(sbase + s * 8, ph);
            const uint32_t sa = stg + s * STAGE_BYTES;       // compile-time s
            const uint32_t sb = sa + CHUNK_BYTES;

#pragma unroll
            for (int ks = 0; ks < 2; ks++) {
                uint32_t af[4][4];
#pragma unroll
                for (int mt = 0; mt < 4; mt++)
                    ldsm_x4(af[mt], sa + sw_off(a_row + mt * 16, ks * 2 + a_gsel));
                uint32_t bf[2][4];
#pragma unroll
                for (int h = 0; h < 2; h++)
                    ldsm_x4(bf[h], sb + sw_off(b_row + h * 16, ks * 2 + b_gsel));
#pragma unroll
                for (int mt = 0; mt < 4; mt++)
#pragma unroll
                    for (int nt = 0; nt < 4; nt++)
                        mma16816(acc[mt][nt], af[mt], &bf[nt >> 1][(nt & 1) * 2]);
            }

            if (lid == 0) mbar_arrive(sbase + 64 + s * 8);
            if (tid == 0 && kb + s + NSTAGE < NCH) {
                mbar_wait(sbase + 64 + s * 8, ph);
                const int nk = kb + s + NSTAGE;
                mbar_expect_tx(sbase + s * 8, STAGE_BYTES);
                bulk_g2s(stg + s * STAGE_BYTES,               Asrc + ((size_t)nk << 13),
                         CHUNK_BYTES, sbase + s * 8);
                bulk_g2s(stg + s * STAGE_BYTES + CHUNK_BYTES, Bsrc + ((size_t)nk << 13),
                         CHUNK_BYTES, sbase + s * 8);
            }
        }
    }

    // ---------------- epilogue: dist + top-2 ----------------
    const float* ga = g_a + mtile * BM;
    float v1[8], v2[8];
    int i1[8];
#pragma unroll
    for (int i = 0; i < 8; i++) {
        v1[i] = __int_as_float(0x7f800000);
        v2[i] = __int_as_float(0x7f800000);
        i1[i] = 0;
    }

#pragma unroll
    for (int mt = 0; mt < 4; mt++)
#pragma unroll
        for (int rh = 0; rh < 2; rh++) {
            const int r = mt * 2 + rh;
            const float a = ga[wm * 64 + mt * 16 + g + rh * 8];
#pragma unroll
            for (int nt = 0; nt < 4; nt++)
#pragma unroll
                for (int cc = 0; cc < 2; cc++) {
                    const float b = acc[mt][nt][rh * 2 + cc];
                    const int n = ntile * BN + wn * 32 + nt * 8 + 2 * tq + cc;
                    const float d = __fadd_rn(__fadd_rn(a, -__fmul_rn(2.0f, b)), g_c[n]);
                    if (d < v1[r]) { v2[r] = v1[r]; v1[r] = d; i1[r] = n; }
                    else if (d < v2[r]) { v2[r] = d; }
                }
        }

#pragma unroll
    for (int i = 0; i < 8; i++) {
#pragma unroll
        for (int ofs = 1; ofs <= 2; ofs <<= 1) {
            const float ov1 = __shfl_xor_sync(0xffffffff, v1[i], ofs);
            const int   oi1 = __shfl_xor_sync(0xffffffff, i1[i], ofs);
            const float ov2 = __shfl_xor_sync(0xffffffff, v2[i], ofs);
            float loser;
            if (ov1 < v1[i] || (ov1 == v1[i] && oi1 < i1[i])) {
                loser = v1[i]; v1[i] = ov1; i1[i] = oi1;
            } else {
                loser = ov1;
            }
            v2[i] = fminf(fminf(v2[i], ov2), loser);
        }
    }

    __syncthreads();
    float* cv1 = reinterpret_cast<float*>(smraw + 1024);
    int*   ci1 = reinterpret_cast<int*>(smraw + 1024 + 2048);
    float* cv2 = reinterpret_cast<float*>(smraw + 1024 + 4096);
    if (tq == 0) {
#pragma unroll
        for (int mt = 0; mt < 4; mt++)
#pragma unroll
            for (int rh = 0; rh < 2; rh++) {
                const int ml = wm * 64 + mt * 16 + g + rh * 8;
                const int r = mt * 2 + rh;
                cv1[ml * 4 + wn] = v1[r];
                ci1[ml * 4 + wn] = i1[r];
                cv2[ml * 4 + wn] = v2[r];
            }
    }
    __syncthreads();
    if (tid < BM) {
        float bv1 = cv1[tid * 4], bv2 = cv2[tid * 4];
        int bi = ci1[tid * 4];
#pragma unroll
        for (int w = 1; w < 4; w++) {
            const float ov1 = cv1[tid * 4 + w], ov2 = cv2[tid * 4 + w];
            const int oi = ci1[tid * 4 + w];
            float loser;
            if (ov1 < bv1 || (ov1 == bv1 && oi < bi)) { loser = bv1; bv1 = ov1; bi = oi; }
            else loser = ov1;
            bv2 = fminf(fminf(bv2, ov2), loser);
        }
        const size_t slot = (size_t)(mtile * BM + tid) * NNT + ntile;
        g_cand1[slot] = ((unsigned long long)__float_as_uint(bv1) << 32) | (unsigned)bi;
        g_cand2[slot] = bv2;
    }
}

// =====================================================================
// Launch 5 — flag: near-ties -> refine list; store best value.
// =====================================================================
__global__ void flag_kernel() {
    const int tid = threadIdx.x, lane = tid & 31;
    const int m = blockIdx.x * 8 + (tid >> 5);

    unsigned long long key = g_cand1[(size_t)m * NNT + lane];
    float mv2 = g_cand2[(size_t)m * NNT + lane];

    unsigned long long bkey = key;
#pragma unroll
    for (int o = 16; o; o >>= 1) {
        unsigned long long ok = __shfl_xor_sync(0xffffffff, bkey, o);
        if (ok < bkey) bkey = ok;
    }
    const float bv = __uint_as_float((unsigned)(bkey >> 32));
    float cand2 = (key == bkey) ? mv2 : fminf(__uint_as_float((unsigned)(key >> 32)), mv2);
#pragma unroll
    for (int o = 16; o; o >>= 1)
        cand2 = fminf(cand2, __shfl_xor_sync(0xffffffff, cand2, o));

    if (lane == 0) {
        g_idx[m] = (int)(bkey & 0xffffffffu);
        if (__fadd_rn(cand2, -bv) < THRESH) {
            g_key2[m] = ~0ull;
            g_bestv[m] = bv;
            const int pos = atomicAdd(&g_cnt, 1);
            g_list[pos] = m;
        }
    }
}

// =====================================================================
// Launch 6 — refine: tile-restricted exact refine (128-code tiles).
// =====================================================================
__global__ void __launch_bounds__(128) refine_kernel(const float* __restrict__ x) {
    __shared__ float xs[DIM];
    __shared__ float wv[4];
    __shared__ int   wi[4];
    const int nt = blockIdx.x & 31;
    const int slot = blockIdx.x >> 5;
    const int t = threadIdx.x;
    const int cnt = g_cnt;

    for (int ri = slot; ri < cnt; ri += 1024) {
        const int m = g_list[ri];
        const float c1v =
            __uint_as_float((unsigned)(g_cand1[(size_t)m * NNT + nt] >> 32));
        if (c1v > __fadd_rn(g_bestv[m], THRESH)) continue;

        __syncthreads();
        {
            float4 v = reinterpret_cast<const float4*>(x + (size_t)m * DIM)[t];
            xs[4 * t + 0] = v.x;
            xs[4 * t + 1] = v.y;
            xs[4 * t + 2] = v.z;
            xs[4 * t + 3] = v.w;
        }
        __syncthreads();

        const int n = nt * 128 + t;
        float b = 0.0f;
#pragma unroll 8
        for (int k = 0; k < DIM; k++)
            b = __fmaf_rn(xs[k], g_whatT[(size_t)k * NCODES + n], b);
        float v = __fadd_rn(__fadd_rn(g_a[m], -__fmul_rn(2.0f, b)), g_c[n]);
        int ix = n;

#pragma unroll
        for (int o = 16; o; o >>= 1) {
            const float ov = __shfl_xor_sync(0xffffffff, v, o);
            const int oi = __shfl_xor_sync(0xffffffff, ix, o);
            if (ov < v || (ov == v && oi < ix)) { v = ov; ix = oi; }
        }
        if ((t & 31) == 0) { wv[t >> 5] = v; wi[t >> 5] = ix; }
        __syncthreads();
        if (t == 0) {
#pragma unroll
            for (int w2 = 1; w2 < 4; w2++) {
                if (wv[w2] < v || (wv[w2] == v && wi[w2] < ix)) { v = wv[w2]; ix = wi[w2]; }
            }
            atomicMin(&g_key2[m],
                      ((unsigned long long)__float_as_uint(v) << 32) | (unsigned)ix);
        }
    }
}

// launch 7
__global__ void apply_kernel() {
    const int cnt = g_cnt;
    for (int i = blockIdx.x * 256 + threadIdx.x; i < cnt; i += gridDim.x * 256) {
        const int m = g_list[i];
        g_idx[m] = (int)(g_key2[m] & 0xffffffffu);
    }
}

// =====================================================================
// Launch 8 — gather: fp32 per-thread diff partials.
// =====================================================================
__global__ void gather_kernel(const float* __restrict__ x,
                              const float* __restrict__ ew,
                              float* __restrict__ out) {
    __shared__ double ss[8];
    const int w = threadIdx.x >> 5, l = threadIdx.x & 31;
    const int m = blockIdx.x * 8 + w;
    const int idx = g_idx[m];

    const float4* qr = reinterpret_cast<const float4*>(ew + (size_t)idx * DIM);
    const float4* xr = reinterpret_cast<const float4*>(x + (size_t)m * DIM);
    float4* orow = reinterpret_cast<float4*>(out) + (size_t)m * (DIM / 4);

    float sf = 0.0f;
#pragma unroll
    for (int p = 0; p < 4; p++) {
        const int c = l + p * 32;
        float4 q = qr[c];
        float4 xv = xr[c];
        float4 o;
        float e, q1;
        e = __fadd_rn(q.x, -xv.x); q1 = __fadd_rn(xv.x, e);
        o.x = __fmul_rn(__fadd_rn(q.x, q1), 0.5f); sf = __fmaf_rn(e, e, sf);
        e = __fadd_rn(q.y, -xv.y); q1 = __fadd_rn(xv.y, e);
        o.y = __fmul_rn(__fadd_rn(q.y, q1), 0.5f); sf = __fmaf_rn(e, e, sf);
        e = __fadd_rn(q.z, -xv.z); q1 = __fadd_rn(xv.z, e);
        o.z = __fmul_rn(__fadd_rn(q.z, q1), 0.5f); sf = __fmaf_rn(e, e, sf);
        e = __fadd_rn(q.w, -xv.w); q1 = __fadd_rn(xv.w, e);
        o.w = __fmul_rn(__fadd_rn(q.w, q1), 0.5f); sf = __fmaf_rn(e, e, sf);
        orow[c] = o;
    }
    double s = (double)sf;
#pragma unroll
    for (int o = 16; o; o >>= 1)
        s += __shfl_xor_sync(0xffffffff, s, o);
    if (l == 0) ss[w] = s;
    __syncthreads();
    if (threadIdx.x == 0) {
        double t = 0.0;
#pragma unroll
        for (int i = 0; i < 8; i++) t += ss[i];
        atomicAdd(&g_diff, t);
    }
}

// launch 9
__global__ void final_kernel(float* __restrict__ out, int write_scalar) {
    if (write_scalar)
        out[(size_t)M_ROWS * DIM] = (float)(g_diff / (double)((size_t)M_ROWS * DIM));
}

// =====================================================================
extern "C" void kernel_launch(void* const* d_in, const int* in_sizes, int n_in,
                              void* d_out, int out_size) {
    const float* x  = (const float*)d_in[0];
    const float* ew = (const float*)d_in[1];
    if (n_in >= 2 && in_sizes[0] == NCODES * DIM && in_sizes[1] == M_ROWS * DIM) {
        ew = (const float*)d_in[0];
        x  = (const float*)d_in[1];
    }
    float* out = (float*)d_out;

    cudaFuncSetAttribute(mma_topcand_kernel,
                         cudaFuncAttributeMaxDynamicSharedMemorySize, SMEM_BYTES);

    xprep_kernel<<<M_ROWS / 32, 256>>>(x);                    // 1
    prepw_kernel<<<NCODES, 128>>>(ew);                        // 2
    transpose_kernel<<<2048, 256>>>();                        // 3
    mma_topcand_kernel<<<NMT * NNT, TPB, SMEM_BYTES>>>();     // 4 <- profiled
    flag_kernel<<<M_ROWS / 8, 256>>>();                       // 5
    refine_kernel<<<32 * 1024, 128>>>(x);                     // 6
    apply_kernel<<<32, 256>>>();                              // 7
    gather_kernel<<<M_ROWS / 8, 256>>>(x, ew, out);           // 8
    const int write_scalar = (out_size > M_ROWS * DIM) ? 1 : 0;
    final_kernel<<<1, 1>>>(out, write_scalar);                // 9
}